// round 1
// baseline (speedup 1.0000x reference)
#include <cuda_runtime.h>

#define THRESH 0.3f
#define MARGIN 0.1f
#define WEIGHT 0.1f

constexpr int NBLOCKS  = 2048;
constexpr int NTHREADS = 256;

// Scratch for deterministic two-pass reduction (no device allocation allowed).
__device__ float        g_psum[NBLOCKS];
__device__ unsigned int g_pcnt[NBLOCKS];

__global__ __launch_bounds__(NTHREADS)
void tcl_stage1(const float4* __restrict__ pred,   // (B,4) as float4 rows
                const float*  __restrict__ times,  // (B,)
                int B)
{
    float        sum = 0.0f;
    unsigned int cnt = 0;

    const int stride = gridDim.x * blockDim.x;
    int i = blockIdx.x * blockDim.x + threadIdx.x;

    #pragma unroll 4
    for (; i < B; i += stride) {
        float4 p = pred[i];        // p.x unused (predictions[:,0])
        float  t = times[i];
        float p4 = p.y, p5 = p.z, p6 = p.w;

        bool a = p4 > THRESH;
        bool b = p5 > THRESH;
        bool c = p6 > THRESH;
        bool m45  = a && b;
        bool m56  = b && c;
        bool m456 = m45 && c;

        if (m45) {
            // exactly as reference: relu(MARGIN - (p5*t - p4*t))
            sum += fmaxf(MARGIN - (p5 * t - p4 * t), 0.0f);
            cnt++;
        }
        if (m56) {
            sum += fmaxf(MARGIN - (p6 * t - p5 * t), 0.0f);
            cnt++;
        }
        if (m456) {
            float d45 = fabsf(p5 - p4);
            float d56 = fabsf(p6 - p5);
            sum += fmaxf(d45 - d56 + MARGIN, 0.0f);
            cnt++;
        }
    }

    // Warp reduce
    #pragma unroll
    for (int off = 16; off > 0; off >>= 1) {
        sum += __shfl_down_sync(0xFFFFFFFFu, sum, off);
        cnt += __shfl_down_sync(0xFFFFFFFFu, cnt, off);
    }

    __shared__ float        s_sum[NTHREADS / 32];
    __shared__ unsigned int s_cnt[NTHREADS / 32];
    int lane = threadIdx.x & 31;
    int wid  = threadIdx.x >> 5;
    if (lane == 0) { s_sum[wid] = sum; s_cnt[wid] = cnt; }
    __syncthreads();

    if (wid == 0) {
        sum = (lane < NTHREADS / 32) ? s_sum[lane] : 0.0f;
        cnt = (lane < NTHREADS / 32) ? s_cnt[lane] : 0u;
        #pragma unroll
        for (int off = 4; off > 0; off >>= 1) {
            sum += __shfl_down_sync(0xFFFFFFFFu, sum, off);
            cnt += __shfl_down_sync(0xFFFFFFFFu, cnt, off);
        }
        if (lane == 0) {
            g_psum[blockIdx.x] = sum;
            g_pcnt[blockIdx.x] = cnt;
        }
    }
}

__global__ __launch_bounds__(1024)
void tcl_stage2(float* __restrict__ out)
{
    float        sum = 0.0f;
    unsigned int cnt = 0;

    // 2048 partials / 1024 threads = 2 each (fixed order -> deterministic)
    for (int i = threadIdx.x; i < NBLOCKS; i += 1024) {
        sum += g_psum[i];
        cnt += g_pcnt[i];
    }

    #pragma unroll
    for (int off = 16; off > 0; off >>= 1) {
        sum += __shfl_down_sync(0xFFFFFFFFu, sum, off);
        cnt += __shfl_down_sync(0xFFFFFFFFu, cnt, off);
    }

    __shared__ float        s_sum[32];
    __shared__ unsigned int s_cnt[32];
    int lane = threadIdx.x & 31;
    int wid  = threadIdx.x >> 5;
    if (lane == 0) { s_sum[wid] = sum; s_cnt[wid] = cnt; }
    __syncthreads();

    if (wid == 0) {
        sum = (lane < 32) ? s_sum[lane] : 0.0f;
        cnt = (lane < 32) ? s_cnt[lane] : 0u;
        #pragma unroll
        for (int off = 16; off > 0; off >>= 1) {
            sum += __shfl_down_sync(0xFFFFFFFFu, sum, off);
            cnt += __shfl_down_sync(0xFFFFFFFFu, cnt, off);
        }
        if (lane == 0) {
            float count = (float)cnt;
            float loss  = (count > 0.0f) ? (sum / fmaxf(count, 1.0f)) : sum;
            out[0] = WEIGHT * loss;
        }
    }
}

extern "C" void kernel_launch(void* const* d_in, const int* in_sizes, int n_in,
                              void* d_out, int out_size)
{
    const float4* pred  = (const float4*)d_in[0];  // (B,4) float32
    const float*  times = (const float*)d_in[1];   // (B,1) float32
    float*        out   = (float*)d_out;

    int B = in_sizes[1];  // element count of relative_times = B

    tcl_stage1<<<NBLOCKS, NTHREADS>>>(pred, times, B);
    tcl_stage2<<<1, 1024>>>(out);
}